// round 15
// baseline (speedup 1.0000x reference)
#include <cuda_runtime.h>

// ProbAttention (Informer ProbSparse) for B=2, L=4096, H=8, D=64, sample_k = n_top = 45.

#define Bb   2
#define Ll   4096
#define Hh   8
#define Dd   64
#define SSK  45          // sample_k == n_top
#define BH   (Bb*Hh)     // 16
#define NC   16          // kv chunks in k3
#define CK   256         // keys per chunk in k3
#define SST  257         // padded ss row stride (floats)
#define KC   256         // keys per chunk in k1
#define NKC  16          // Ll / KC

typedef unsigned long long ull;

// ---- scratch (static device globals: no allocation allowed) ----
__device__ int    g_idx_is64;
__device__ __align__(8) unsigned char g_boff8[NKC * Ll];  // chunk-major bucket offsets
__device__ int    g_bidx[Ll * SSK];                       // bucketed sample indices
__device__ float2 g_pMS[BH * NKC * Ll];                   // per-chunk (max, sum)
__device__ int    g_top[BH * SSK];
__device__ float  g_pmax[BH * NC * SSK];
__device__ float  g_psum[BH * NC * SSK];
__device__ float4 g_pout[BH * NC * SSK * (Dd / 4)];
__device__ int    g_cnt[BH];

// ---- f32x2 packed-FMA helpers ----
__device__ __forceinline__ ull fma2(ull a, ull b, ull c) {
    ull d;
    asm("fma.rn.f32x2 %0, %1, %2, %3;" : "=l"(d) : "l"(a), "l"(b), "l"(c));
    return d;
}
__device__ __forceinline__ ull pack2(float x, float y) {
    ull r;
    asm("mov.b64 %0, {%1, %2};" : "=l"(r) : "f"(x), "f"(y));
    return r;
}
__device__ __forceinline__ void unpack2(ull v, float& x, float& y) {
    asm("mov.b64 {%0, %1}, %2;" : "=f"(x), "=f"(y) : "l"(v));
}

// ---------------- K0: zero output + detect index dtype + reset counters ----------------
__global__ void k0_zero(float4* __restrict__ out4, int n4,
                        const unsigned* __restrict__ idxsrc) {
    if (blockIdx.x == 0) {
        __shared__ int nz;
        if (threadIdx.x == 0) nz = 0;
        __syncthreads();
        if (threadIdx.x < 128) {
            unsigned v = idxsrc[threadIdx.x * 2 + 1];
            if (v != 0u) atomicAdd(&nz, 1);
        }
        __syncthreads();
        if (threadIdx.x == 0) g_idx_is64 = (nz == 0) ? 1 : 0;
        if (threadIdx.x < BH) g_cnt[threadIdx.x] = 0;
    }
    int i = blockIdx.x * 256 + threadIdx.x;
    if (i < n4) out4[i] = make_float4(0.f, 0.f, 0.f, 0.f);
}

// ---------------- KB: bucket sample indices by key-chunk (warp per l) ----------------
__global__ __launch_bounds__(256) void kb_bucket(const void* __restrict__ idxsrc) {
    int l    = blockIdx.x * 8 + (threadIdx.x >> 5);
    int lane = threadIdx.x & 31;
    const int is64 = g_idx_is64;
    const long long* p64 = (const long long*)idxsrc + (size_t)l * SSK;
    const int*       p32 = (const int*)idxsrc + (size_t)l * SSK;

    int s0 = is64 ? (int)p64[lane] : p32[lane];
    bool has1 = lane < (SSK - 32);               // 13 extra lanes
    int s1 = has1 ? (is64 ? (int)p64[lane + 32] : p32[lane + 32]) : 0;
    int c0 = s0 >> 8;                            // KC = 256
    int c1 = has1 ? (s1 >> 8) : -1;

    unsigned lmask = (1u << lane) - 1u;
    int base = 0;
    #pragma unroll
    for (int c = 0; c < NKC; c++) {
        unsigned m0 = __ballot_sync(0xffffffffu, c0 == c);
        unsigned m1 = __ballot_sync(0xffffffffu, c1 == c);
        if (lane == 0) g_boff8[c * Ll + l] = (unsigned char)base;
        if (c0 == c) g_bidx[l * SSK + base + __popc(m0 & lmask)] = s0;
        if (c1 == c) g_bidx[l * SSK + base + __popc(m0) + __popc(m1 & lmask)] = s1;
        base += __popc(m0) + __popc(m1);
    }
}

// ---------------- K1: chunked sampled scoring ----------------
// Grid (NKC, BH), 512 threads. K chunk (256 keys x 64d = 64KB) staged once;
// bucket offsets staged as u8 in smem; per-l sample indices batch-loaded into
// registers and broadcast via shfl; q/index loads pipelined one iter ahead.
#define K1C_SMEM (KC * Dd * 4 + 2 * Ll + 16)
__global__ __launch_bounds__(512) void k1_chunk(const float4* __restrict__ q4,
                                                const float4* __restrict__ k4) {
    int kc = blockIdx.x;
    int bh = blockIdx.y;
    int b = bh >> 3, h = bh & 7;
    int tid = threadIdx.x;

    extern __shared__ char s_raw[];
    float4* ks4 = (float4*)s_raw;                       // [KC][16]
    unsigned char* soff = (unsigned char*)(s_raw + KC * Dd * 4);
    unsigned char* snxt = soff + Ll;

    // stage K chunk (coalesced 256B rows)
    for (int i = tid; i < KC * 16; i += 512) {
        int row = i >> 4, c4 = i & 15;
        ks4[i] = k4[(size_t)(b * Ll + kc * KC + row) * 128 + h * 16 + c4];
    }
    // stage bucket offsets (u8, chunk-major -> coalesced 8B loads)
    {
        const ull* pb = (const ull*)(g_boff8 + (size_t)kc * Ll);
        ((ull*)soff)[tid & 511] = pb[tid & 511];
        if (kc < NKC - 1) {
            const ull* pn = (const ull*)(g_boff8 + (size_t)(kc + 1) * Ll);
            ((ull*)snxt)[tid & 511] = pn[tid & 511];
        } else {
            ((ull*)snxt)[tid & 511] = 0x2D2D2D2D2D2D2D2Dull;  // 45 everywhere
        }
    }
    __syncthreads();

    int wid = tid >> 5, lane = tid & 31;
    int half = lane >> 4, lh = lane & 15;
    float2* pms = g_pMS + (size_t)(bh * NKC + kc) * Ll;

    // software-pipelined loop: 2 l's per warp-iteration, 16 warps
    float4 qv;  int o0, cnt, myidx;
    {   // prologue: load iteration 'wid'
        int l = wid * 2 + half;
        qv = q4[(size_t)(b * Ll + l) * 128 + h * 16 + lh];
        o0 = soff[l];  cnt = (int)snxt[l] - o0;
        myidx = (lh < cnt) ? g_bidx[l * SSK + o0 + lh] : 0;
    }
    for (int it = wid; it < Ll / 2; it += 16) {
        float4 qv2;  int o02 = 0, cnt2 = 0, mi2 = 0;
        if (it + 16 < Ll / 2) {   // prefetch next iteration
            int l2 = (it + 16) * 2 + half;
            qv2 = q4[(size_t)(b * Ll + l2) * 128 + h * 16 + lh];
            o02 = soff[l2];  cnt2 = (int)snxt[l2] - o02;
            mi2 = (lh < cnt2) ? g_bidx[l2 * SSK + o02 + lh] : 0;
        } else {
            qv2 = make_float4(0.f, 0.f, 0.f, 0.f);
        }

        int l = it * 2 + half;
        float mx = -1e30f, sm = 0.f;
        int nb = cnt < 16 ? cnt : 16;
        for (int s = 0; s < nb; s++) {
            int idx = __shfl_sync(0xffffffffu, myidx, (half << 4) + s) - kc * KC;
            float4 kv = ks4[idx * 16 + lh];
            float p = qv.x*kv.x + qv.y*kv.y + qv.z*kv.z + qv.w*kv.w;
            p += __shfl_xor_sync(0xffffffffu, p, 8);
            p += __shfl_xor_sync(0xffffffffu, p, 4);
            p += __shfl_xor_sync(0xffffffffu, p, 2);
            p += __shfl_xor_sync(0xffffffffu, p, 1);
            mx = fmaxf(mx, p);
            sm += p;
        }
        // rare slow path: more than 16 samples in this chunk
        for (int base = 16; base < cnt; base += 16) {
            int rem = cnt - base;
            int mi = (lh < rem) ? g_bidx[l * SSK + o0 + base + lh] : 0;
            int ne = rem < 16 ? rem : 16;
            for (int s = 0; s < ne; s++) {
                int idx = __shfl_sync(0xffffffffu, mi, (half << 4) + s) - kc * KC;
                float4 kv = ks4[idx * 16 + lh];
                float p = qv.x*kv.x + qv.y*kv.y + qv.z*kv.z + qv.w*kv.w;
                p += __shfl_xor_sync(0xffffffffu, p, 8);
                p += __shfl_xor_sync(0xffffffffu, p, 4);
                p += __shfl_xor_sync(0xffffffffu, p, 2);
                p += __shfl_xor_sync(0xffffffffu, p, 1);
                mx = fmaxf(mx, p);
                sm += p;
            }
        }
        if (lh == 0) pms[l] = make_float2(mx, sm);

        qv = qv2;  o0 = o02;  cnt = cnt2;  myidx = mi2;
    }
}

// ---------------- K2: fused partial-combine + top-45 radix select ----------------
__global__ __launch_bounds__(256) void k2_topk() {
    int bh  = blockIdx.x;
    int tid = threadIdx.x;
    int wid = tid >> 5, lane = tid & 31;

    __shared__ unsigned hist[256];
    __shared__ unsigned warptot[8];
    __shared__ unsigned sh_pivot, sh_above;
    __shared__ int n_gt, n_eq;

    // combine NKC partials on the fly, map to order-preserving keys
    unsigned key[16];
    #pragma unroll
    for (int i = 0; i < 16; i++) {
        int l = i * 256 + tid;
        float mx = -1e30f, sm = 0.f;
        #pragma unroll
        for (int kc = 0; kc < NKC; kc++) {
            float2 v = g_pMS[(size_t)(bh * NKC + kc) * Ll + l];
            mx = fmaxf(mx, v.x);
            sm += v.y;
        }
        float M = mx - sm * (1.0f / (float)Ll);
        unsigned u = __float_as_uint(M);
        key[i] = (u & 0x80000000u) ? ~u : (u | 0x80000000u);
    }

    unsigned prefix = 0, pmask = 0;
    int need = SSK;

    #pragma unroll
    for (int round = 0; round < 4; round++) {
        int shift = 24 - round * 8;
        hist[tid] = 0;
        if (tid == 0) { n_gt = 0; n_eq = 0; }
        __syncthreads();
        #pragma unroll
        for (int i = 0; i < 16; i++)
            if ((key[i] & pmask) == prefix)
                atomicAdd(&hist[(key[i] >> shift) & 255u], 1u);
        __syncthreads();

        unsigned x = hist[tid];
        unsigned s = x;
        #pragma unroll
        for (int o = 1; o < 32; o <<= 1) {
            unsigned y = __shfl_down_sync(0xffffffffu, s, o);
            if (lane + o < 32) s += y;
        }
        unsigned wt = __shfl_sync(0xffffffffu, s, 0);
        if (lane == 0) warptot[wid] = wt;
        __syncthreads();
        unsigned hs = 0;
        #pragma unroll
        for (int w2 = 0; w2 < 8; w2++)
            if (w2 > wid) hs += warptot[w2];
        unsigned S = s + hs;
        unsigned above = S - x;
        if ((int)S >= need && (int)above < need) {
            sh_pivot = (unsigned)tid;
            sh_above = above;
        }
        __syncthreads();
        prefix |= sh_pivot << shift;
        pmask  |= 0xffu << shift;
        need   -= (int)sh_above;
        __syncthreads();
    }

    int base = bh * SSK;
    #pragma unroll
    for (int i = 0; i < 16; i++)
        if (key[i] > prefix) {
            int p = atomicAdd(&n_gt, 1);
            g_top[base + p] = i * 256 + tid;
        }
    __syncthreads();
    int gt = n_gt;
    #pragma unroll
    for (int i = 0; i < 16; i++)
        if (key[i] == prefix) {
            int e = atomicAdd(&n_eq, 1);
            if (e < need) g_top[base + gt + e] = i * 256 + tid;
        }
}

// ---------------- K3: split-KV sparse attention + fused combine ----------------
#define K3T   256
#define QS2F  (23 * 128)
#define KVF   (CK * 9 * 4)
#define K3_SMEM ((QS2F + KVF + SSK * SST) * 4 + 256)

__global__ __launch_bounds__(K3T, 2) void k3_attn(const float4* __restrict__ q4,
                                                  const float4* __restrict__ k4g,
                                                  const float4* __restrict__ v4g,
                                                  float4* __restrict__ out4) {
    int c  = blockIdx.x;
    int bh = blockIdx.y;
    int b = bh >> 3, h = bh & 7;
    int tid = threadIdx.x;

    extern __shared__ float smem[];
    float* qs2f = smem;
    float* kv   = qs2f + QS2F;
    float* ss   = kv + KVF;
    int*   tops = (int*)(ss + SSK * SST);
    float4*           kv4 = (float4*)kv;
    const ulonglong2* kvU = (const ulonglong2*)kv;
    const ulonglong2* qsU = (const ulonglong2*)qs2f;

    if (tid < SSK) tops[tid] = g_top[bh * SSK + tid];
    __syncthreads();

    // stage Q in u-pair-packed layout
    for (int i = tid; i < 46 * 16; i += K3T) {
        int u = i >> 4, c4 = i & 15;
        float4 qv = (u < SSK)
            ? q4[((size_t)(b * Ll + tops[u]) * Hh + h) * (Dd / 4) + c4]
            : make_float4(0.f, 0.f, 0.f, 0.f);
        float* dst = qs2f + ((u >> 1) * 128 + 8 * c4) + (u & 1);
        dst[0] = qv.x; dst[2] = qv.y; dst[4] = qv.z; dst[6] = qv.w;
    }

    int k0 = c * CK;
    int j = tid;

    // S-phase: acc for 23 u-pairs in registers, K staged in two 32-dim chunks
    ull acc[23];
    #pragma unroll
    for (int i = 0; i < 23; i++) acc[i] = 0ull;

    #pragma unroll 1
    for (int cc = 0; cc < 2; cc++) {
        __syncthreads();
        for (int i = tid; i < CK * 8; i += K3T) {
            int row = i >> 3, dc = i & 7;
            kv4[row * 9 + dc] =
                k4g[((size_t)(b * Ll + k0 + row) * Hh + h) * 16 + cc * 8 + dc];
        }
        __syncthreads();
        #pragma unroll 1
        for (int dc = 0; dc < 8; dc++) {
            float4 kr = kv4[j * 9 + dc];
            ull kk0 = pack2(kr.x, kr.x);
            ull kk1 = pack2(kr.y, kr.y);
            ull kk2 = pack2(kr.z, kr.z);
            ull kk3 = pack2(kr.w, kr.w);
            int dcg = cc * 8 + dc;
            #pragma unroll
            for (int i = 0; i < 23; i++) {
                ulonglong2 qA = qsU[i * 32 + dcg * 2];
                ulonglong2 qB = qsU[i * 32 + dcg * 2 + 1];
                acc[i] = fma2(qA.x, kk0, acc[i]);
                acc[i] = fma2(qA.y, kk1, acc[i]);
                acc[i] = fma2(qB.x, kk2, acc[i]);
                acc[i] = fma2(qB.y, kk3, acc[i]);
            }
        }
    }
    #pragma unroll
    for (int i = 0; i < 23; i++) {
        float lo, hi;
        unpack2(acc[i], lo, hi);
        ss[(2 * i) * SST + j] = lo;
        if (2 * i + 1 < SSK) ss[(2 * i + 1) * SST + j] = hi;
    }
    __syncthreads();   // ss visible; kv buffer free

    // stage V chunk 0 (overlaps with softmax)
    for (int i = tid; i < 128 * 16; i += K3T) {
        int row = i >> 4, c4 = i & 15;
        kv4[row * 17 + c4] =
            v4g[((size_t)(b * Ll + k0 + row) * Hh + h) * 16 + c4];
    }

    // partial softmax per row u (warp-per-row, 8 warps)
    int wid = tid >> 5, lane = tid & 31;
    for (int u = wid; u < SSK; u += 8) {
        float x[8];
        float mxv = -1e30f;
        #pragma unroll
        for (int t = 0; t < 8; t++) { x[t] = ss[u * SST + lane + t * 32]; mxv = fmaxf(mxv, x[t]); }
        #pragma unroll
        for (int o = 16; o; o >>= 1) mxv = fmaxf(mxv, __shfl_xor_sync(0xffffffffu, mxv, o));
        float sum = 0.f;
        #pragma unroll
        for (int t = 0; t < 8; t++) { float p = __expf(0.125f * (x[t] - mxv)); x[t] = p; sum += p; }
        #pragma unroll
        for (int o = 16; o; o >>= 1) sum += __shfl_xor_sync(0xffffffffu, sum, o);
        #pragma unroll
        for (int t = 0; t < 8; t++) ss[u * SST + lane + t * 32] = x[t];
        if (lane == 0) {
            g_pmax[(bh * NC + c) * SSK + u] = 0.125f * mxv;
            g_psum[(bh * NC + c) * SSK + u] = sum;
        }
    }
    __syncthreads();   // softmax ss + V0 staging both complete

    // P@V: thread = (ug, d4); ug<15 owns u = {3ug, 3ug+1, 3ug+2}
    int d4 = tid & 15, ug = tid >> 4;
    int u0 = ug * 3;
    ull a0l = 0, a0h = 0, a1l = 0, a1h = 0, a2l = 0, a2h = 0;

    #pragma unroll 1
    for (int vc = 0; vc < 2; vc++) {
        if (vc) {
            __syncthreads();
            for (int i = tid; i < 128 * 16; i += K3T) {
                int row = i >> 4, c4 = i & 15;
                kv4[row * 17 + c4] =
                    v4g[((size_t)(b * Ll + k0 + 128 + row) * Hh + h) * 16 + c4];
            }
            __syncthreads();
        }
        if (ug < 15) {
            #pragma unroll 4
            for (int jj = 0; jj < 128; jj++) {
                ulonglong2 vv = kvU[jj * 17 + d4];
                int jg = vc * 128 + jj;
                float p0 = ss[u0 * SST + jg];
                float p1 = ss[(u0 + 1) * SST + jg];
                float p2 = ss[(u0 + 2) * SST + jg];
                ull b0 = pack2(p0, p0), b1 = pack2(p1, p1), b2 = pack2(p2, p2);
                a0l = fma2(b0, vv.x, a0l);  a0h = fma2(b0, vv.y, a0h);
                a1l = fma2(b1, vv.x, a1l);  a1h = fma2(b1, vv.y, a1h);
                a2l = fma2(b2, vv.x, a2l);  a2h = fma2(b2, vv.y, a2h);
            }
        }
    }
    if (ug < 15) {
        ulonglong2* po = (ulonglong2*)g_pout;
        size_t baseo = ((size_t)(bh * NC + c) * SSK) * 16 + d4;
        po[baseo + (size_t)u0 * 16]       = make_ulonglong2(a0l, a0h);
        po[baseo + (size_t)(u0 + 1) * 16] = make_ulonglong2(a1l, a1h);
        po[baseo + (size_t)(u0 + 2) * 16] = make_ulonglong2(a2l, a2h);
    }

    // ---- fused combine: last CTA of this bh merges partials and scatters ----
    __threadfence();
    __syncthreads();
    __shared__ int s_last;
    if (tid == 0) s_last = (atomicAdd(&g_cnt[bh], 1) == NC - 1) ? 1 : 0;
    __syncthreads();
    if (!s_last) return;
    __threadfence();

    for (int i = tid; i < SSK * 16; i += K3T) {
        int u = i >> 4, dq = i & 15;
        float gm = -1e30f;
        #pragma unroll
        for (int cc = 0; cc < NC; cc++)
            gm = fmaxf(gm, g_pmax[(bh * NC + cc) * SSK + u]);
        float denom = 0.f;
        float4 a = make_float4(0.f, 0.f, 0.f, 0.f);
        #pragma unroll
        for (int cc = 0; cc < NC; cc++) {
            float w = __expf(g_pmax[(bh * NC + cc) * SSK + u] - gm);
            denom += g_psum[(bh * NC + cc) * SSK + u] * w;
            float4 po = g_pout[((bh * NC + cc) * SSK + u) * 16 + dq];
            a.x += w * po.x; a.y += w * po.y; a.z += w * po.z; a.w += w * po.w;
        }
        float inv = 1.0f / denom;
        a.x *= inv; a.y *= inv; a.z *= inv; a.w *= inv;
        int lsel = tops[u];
        out4[((size_t)(b * Ll + lsel) * Hh + h) * 16 + dq] = a;
    }
}

// ---------------- launch ----------------
extern "C" void kernel_launch(void* const* d_in, const int* in_sizes, int n_in,
                              void* d_out, int out_size) {
    const float4* q4 = (const float4*)d_in[0];
    const float4* k4 = (const float4*)d_in[1];
    const float4* v4 = (const float4*)d_in[2];
    const void* idxp = d_in[n_in - 1];
    for (int i = 0; i < n_in; i++)
        if (in_sizes[i] == Ll * SSK) idxp = d_in[i];
    float4* out4 = (float4*)d_out;

    cudaFuncSetAttribute(k1_chunk, cudaFuncAttributeMaxDynamicSharedMemorySize, K1C_SMEM);
    cudaFuncSetAttribute(k3_attn, cudaFuncAttributeMaxDynamicSharedMemorySize, K3_SMEM);

    int n4 = out_size / 4;
    k0_zero<<<(n4 + 255) / 256, 256>>>(out4, n4, (const unsigned*)idxp);
    kb_bucket<<<Ll / 8, 256>>>(idxp);
    k1_chunk<<<dim3(NKC, BH), 512, K1C_SMEM>>>(q4, k4);
    k2_topk<<<BH, 256>>>();
    k3_attn<<<dim3(NC, BH), K3T, K3_SMEM>>>(q4, k4, v4, out4);
}

// round 16
// speedup vs baseline: 4.5365x; 4.5365x over previous
#include <cuda_runtime.h>

// ProbAttention (Informer ProbSparse) for B=2, L=4096, H=8, D=64, sample_k = n_top = 45.

#define Bb   2
#define Ll   4096
#define Hh   8
#define Dd   64
#define SSK  45          // sample_k == n_top
#define BH   (Bb*Hh)     // 16
#define NC   16          // kv chunks in phase 3
#define CK   256         // keys per chunk in k3
#define SST  260         // padded ss row stride (floats; 65 float4, odd f4-stride)
#define SST4 (SST/4)

typedef unsigned long long ull;

// ---- scratch (static device globals: no allocation allowed) ----
__device__ int    g_idx_is64;
__device__ float  g_M[BH * Ll];
__device__ int    g_top[BH * SSK];
__device__ float  g_pmax[BH * NC * SSK];
__device__ float  g_psum[BH * NC * SSK];
__device__ float4 g_pout[BH * NC * SSK * (Dd / 4)];
__device__ int    g_cnt[BH];             // k3 completion counters (reset each launch)

// ---- f32x2 packed-FMA helpers ----
__device__ __forceinline__ ull fma2(ull a, ull b, ull c) {
    ull d;
    asm("fma.rn.f32x2 %0, %1, %2, %3;" : "=l"(d) : "l"(a), "l"(b), "l"(c));
    return d;
}
__device__ __forceinline__ ull pack2(float x, float y) {
    ull r;
    asm("mov.b64 %0, {%1, %2};" : "=l"(r) : "f"(x), "f"(y));
    return r;
}
__device__ __forceinline__ void unpack2(ull v, float& x, float& y) {
    asm("mov.b64 {%0, %1}, %2;" : "=f"(x), "=f"(y) : "l"(v));
}

// ---------------- K0: zero output + detect index dtype + reset counters ----------------
__global__ void k0_zero(float4* __restrict__ out4, int n4,
                        const unsigned* __restrict__ idxsrc) {
    if (blockIdx.x == 0) {
        __shared__ int nz;
        if (threadIdx.x == 0) nz = 0;
        __syncthreads();
        if (threadIdx.x < 128) {
            unsigned v = idxsrc[threadIdx.x * 2 + 1];
            if (v != 0u) atomicAdd(&nz, 1);
        }
        __syncthreads();
        if (threadIdx.x == 0) g_idx_is64 = (nz == 0) ? 1 : 0;
        if (threadIdx.x < BH) g_cnt[threadIdx.x] = 0;
    }
    int i = blockIdx.x * 256 + threadIdx.x;
    if (i < n4) out4[i] = make_float4(0.f, 0.f, 0.f, 0.f);
}

// ---------------- K1: sampled scores M ----------------
// One warp per (b,l); 8 heads at once; fully coalesced 512B loads per step.
// 128-thread blocks (grid 2048); index loads software-pipelined one ahead.
__global__ __launch_bounds__(128) void k1_score(const float4* __restrict__ q4,
                                                const float4* __restrict__ k4,
                                                const void* __restrict__ idxsrc) {
    int w    = blockIdx.x * 4 + (threadIdx.x >> 5);
    int lane = threadIdx.x & 31;
    int b = w >> 12;
    int l = w & (Ll - 1);

    const float4* qp = q4 + (size_t)(b * Ll + l) * (Hh * Dd / 4);
    float4 qv[4];
    #pragma unroll
    for (int t = 0; t < 4; t++) qv[t] = qp[t * 32 + lane];

    float mx[4] = {-1e30f, -1e30f, -1e30f, -1e30f};
    float sm[4] = {0.f, 0.f, 0.f, 0.f};

    const int is64 = g_idx_is64;
    const long long* ip64 = (const long long*)idxsrc + (size_t)l * SSK;
    const int*       ip32 = (const int*)idxsrc + (size_t)l * SSK;

    int idx = is64 ? (int)ip64[0] : ip32[0];
    #pragma unroll 3
    for (int s = 0; s < SSK; s++) {
        int nidx = (s + 1 < SSK) ? (is64 ? (int)ip64[s + 1] : ip32[s + 1]) : 0;
        const float4* kp = k4 + (size_t)(b * Ll + idx) * (Hh * Dd / 4);
        #pragma unroll
        for (int t = 0; t < 4; t++) {
            float4 kv = kp[t * 32 + lane];
            float p = qv[t].x*kv.x + qv[t].y*kv.y + qv[t].z*kv.z + qv[t].w*kv.w;
            p += __shfl_xor_sync(0xffffffffu, p, 8);
            p += __shfl_xor_sync(0xffffffffu, p, 4);
            p += __shfl_xor_sync(0xffffffffu, p, 2);
            p += __shfl_xor_sync(0xffffffffu, p, 1);
            mx[t] = fmaxf(mx[t], p);
            sm[t] += p;
        }
        idx = nidx;
    }
    if ((lane & 15) == 0) {
        int half = lane >> 4;
        #pragma unroll
        for (int t = 0; t < 4; t++) {
            int h = 2 * t + half;
            g_M[(b * Hh + h) * Ll + l] = mx[t] - sm[t] * (1.0f / (float)Ll);
        }
    }
}

// ---------------- K2: top-45 per (b,h) via 4-round radix select ----------------
__global__ __launch_bounds__(256) void k2_topk() {
    int bh  = blockIdx.x;
    int tid = threadIdx.x;
    int wid = tid >> 5, lane = tid & 31;

    __shared__ unsigned hist[256];
    __shared__ unsigned warptot[8];
    __shared__ unsigned sh_pivot, sh_above;
    __shared__ int n_gt, n_eq;

    unsigned key[16];
    #pragma unroll
    for (int i = 0; i < 16; i++) {
        unsigned u = __float_as_uint(g_M[bh * Ll + i * 256 + tid]);
        key[i] = (u & 0x80000000u) ? ~u : (u | 0x80000000u);
    }

    unsigned prefix = 0, pmask = 0;
    int need = SSK;

    #pragma unroll
    for (int round = 0; round < 4; round++) {
        int shift = 24 - round * 8;
        hist[tid] = 0;
        if (tid == 0) { n_gt = 0; n_eq = 0; }
        __syncthreads();
        #pragma unroll
        for (int i = 0; i < 16; i++)
            if ((key[i] & pmask) == prefix)
                atomicAdd(&hist[(key[i] >> shift) & 255u], 1u);
        __syncthreads();

        unsigned x = hist[tid];
        unsigned s = x;
        #pragma unroll
        for (int o = 1; o < 32; o <<= 1) {
            unsigned y = __shfl_down_sync(0xffffffffu, s, o);
            if (lane + o < 32) s += y;
        }
        unsigned wt = __shfl_sync(0xffffffffu, s, 0);
        if (lane == 0) warptot[wid] = wt;
        __syncthreads();
        unsigned hs = 0;
        #pragma unroll
        for (int w2 = 0; w2 < 8; w2++)
            if (w2 > wid) hs += warptot[w2];
        unsigned S = s + hs;
        unsigned above = S - x;
        if ((int)S >= need && (int)above < need) {
            sh_pivot = (unsigned)tid;
            sh_above = above;
        }
        __syncthreads();
        prefix |= sh_pivot << shift;
        pmask  |= 0xffu << shift;
        need   -= (int)sh_above;
        __syncthreads();
    }

    int base = bh * SSK;
    #pragma unroll
    for (int i = 0; i < 16; i++)
        if (key[i] > prefix) {
            int p = atomicAdd(&n_gt, 1);
            g_top[base + p] = i * 256 + tid;
        }
    __syncthreads();
    int gt = n_gt;
    #pragma unroll
    for (int i = 0; i < 16; i++)
        if (key[i] == prefix) {
            int e = atomicAdd(&n_eq, 1);
            if (e < need) g_top[base + gt + e] = i * 256 + tid;
        }
}

// ---------------- K3: split-KV sparse attention + fused combine ----------------
#define K3T   256
#define QS2F  (23 * 128)
#define KVF   (CK * 9 * 4)
#define K3_SMEM ((QS2F + KVF + SSK * SST) * 4 + 256)

__global__ __launch_bounds__(K3T, 2) void k3_attn(const float4* __restrict__ q4,
                                                  const float4* __restrict__ k4g,
                                                  const float4* __restrict__ v4g,
                                                  float4* __restrict__ out4) {
    int c  = blockIdx.x;
    int bh = blockIdx.y;
    int b = bh >> 3, h = bh & 7;
    int tid = threadIdx.x;

    extern __shared__ float smem[];
    float* qs2f = smem;
    float* kv   = qs2f + QS2F;
    float* ss   = kv + KVF;
    int*   tops = (int*)(ss + SSK * SST);
    float4*           kv4 = (float4*)kv;
    const ulonglong2* kvU = (const ulonglong2*)kv;
    const ulonglong2* qsU = (const ulonglong2*)qs2f;
    const float4*     ss4 = (const float4*)ss;

    if (tid < SSK) tops[tid] = g_top[bh * SSK + tid];
    __syncthreads();

    // stage Q in u-pair-packed layout
    for (int i = tid; i < 46 * 16; i += K3T) {
        int u = i >> 4, c4 = i & 15;
        float4 qv = (u < SSK)
            ? q4[((size_t)(b * Ll + tops[u]) * Hh + h) * (Dd / 4) + c4]
            : make_float4(0.f, 0.f, 0.f, 0.f);
        float* dst = qs2f + ((u >> 1) * 128 + 8 * c4) + (u & 1);
        dst[0] = qv.x; dst[2] = qv.y; dst[4] = qv.z; dst[6] = qv.w;
    }

    int k0 = c * CK;
    int j = tid;

    // S-phase: acc for 23 u-pairs in registers, K staged in two 32-dim chunks
    ull acc[23];
    #pragma unroll
    for (int i = 0; i < 23; i++) acc[i] = 0ull;

    #pragma unroll 1
    for (int cc = 0; cc < 2; cc++) {
        __syncthreads();
        for (int i = tid; i < CK * 8; i += K3T) {
            int row = i >> 3, dc = i & 7;
            kv4[row * 9 + dc] =
                k4g[((size_t)(b * Ll + k0 + row) * Hh + h) * 16 + cc * 8 + dc];
        }
        __syncthreads();
        #pragma unroll 1
        for (int dc = 0; dc < 8; dc++) {
            float4 kr = kv4[j * 9 + dc];
            ull kk0 = pack2(kr.x, kr.x);
            ull kk1 = pack2(kr.y, kr.y);
            ull kk2 = pack2(kr.z, kr.z);
            ull kk3 = pack2(kr.w, kr.w);
            int dcg = cc * 8 + dc;
            #pragma unroll
            for (int i = 0; i < 23; i++) {
                ulonglong2 qA = qsU[i * 32 + dcg * 2];
                ulonglong2 qB = qsU[i * 32 + dcg * 2 + 1];
                acc[i] = fma2(qA.x, kk0, acc[i]);
                acc[i] = fma2(qA.y, kk1, acc[i]);
                acc[i] = fma2(qB.x, kk2, acc[i]);
                acc[i] = fma2(qB.y, kk3, acc[i]);
            }
        }
    }
    #pragma unroll
    for (int i = 0; i < 23; i++) {
        float lo, hi;
        unpack2(acc[i], lo, hi);
        ss[(2 * i) * SST + j] = lo;
        if (2 * i + 1 < SSK) ss[(2 * i + 1) * SST + j] = hi;
    }
    __syncthreads();   // ss visible; kv buffer free

    // stage V chunk 0 (overlaps with softmax)
    for (int i = tid; i < 128 * 16; i += K3T) {
        int row = i >> 4, c4 = i & 15;
        kv4[row * 17 + c4] =
            v4g[((size_t)(b * Ll + k0 + row) * Hh + h) * 16 + c4];
    }

    // partial softmax per row u (warp-per-row, 8 warps)
    int wid = tid >> 5, lane = tid & 31;
    for (int u = wid; u < SSK; u += 8) {
        float x[8];
        float mxv = -1e30f;
        #pragma unroll
        for (int t = 0; t < 8; t++) { x[t] = ss[u * SST + lane + t * 32]; mxv = fmaxf(mxv, x[t]); }
        #pragma unroll
        for (int o = 16; o; o >>= 1) mxv = fmaxf(mxv, __shfl_xor_sync(0xffffffffu, mxv, o));
        float sum = 0.f;
        #pragma unroll
        for (int t = 0; t < 8; t++) { float p = __expf(0.125f * (x[t] - mxv)); x[t] = p; sum += p; }
        #pragma unroll
        for (int o = 16; o; o >>= 1) sum += __shfl_xor_sync(0xffffffffu, sum, o);
        #pragma unroll
        for (int t = 0; t < 8; t++) ss[u * SST + lane + t * 32] = x[t];
        if (lane == 0) {
            g_pmax[(bh * NC + c) * SSK + u] = 0.125f * mxv;
            g_psum[(bh * NC + c) * SSK + u] = sum;
        }
    }
    __syncthreads();   // softmax ss + V0 staging both complete

    // P@V: thread = (ug, d4); ug<15 owns u = {3ug, 3ug+1, 3ug+2};
    // P read as float4 (4 keys per LDS) to cut smem wavefronts.
    int d4 = tid & 15, ug = tid >> 4;
    int u0 = ug * 3;
    ull a0l = 0, a0h = 0, a1l = 0, a1h = 0, a2l = 0, a2h = 0;

    #pragma unroll 1
    for (int vc = 0; vc < 2; vc++) {
        if (vc) {
            __syncthreads();   // PV pass 0 done reading kv
            for (int i = tid; i < 128 * 16; i += K3T) {
                int row = i >> 4, c4 = i & 15;
                kv4[row * 17 + c4] =
                    v4g[((size_t)(b * Ll + k0 + 128 + row) * Hh + h) * 16 + c4];
            }
            __syncthreads();
        }
        if (ug < 15) {
            #pragma unroll 2
            for (int jq = 0; jq < 32; jq++) {
                float4 P0 = ss4[u0 * SST4 + vc * 32 + jq];
                float4 P1 = ss4[(u0 + 1) * SST4 + vc * 32 + jq];
                float4 P2 = ss4[(u0 + 2) * SST4 + vc * 32 + jq];
                #pragma unroll
                for (int t = 0; t < 4; t++) {
                    int jj = jq * 4 + t;
                    ulonglong2 vv = kvU[jj * 17 + d4];
                    float p0 = (t == 0) ? P0.x : (t == 1) ? P0.y : (t == 2) ? P0.z : P0.w;
                    float p1 = (t == 0) ? P1.x : (t == 1) ? P1.y : (t == 2) ? P1.z : P1.w;
                    float p2 = (t == 0) ? P2.x : (t == 1) ? P2.y : (t == 2) ? P2.z : P2.w;
                    ull b0 = pack2(p0, p0), b1 = pack2(p1, p1), b2 = pack2(p2, p2);
                    a0l = fma2(b0, vv.x, a0l);  a0h = fma2(b0, vv.y, a0h);
                    a1l = fma2(b1, vv.x, a1l);  a1h = fma2(b1, vv.y, a1h);
                    a2l = fma2(b2, vv.x, a2l);  a2h = fma2(b2, vv.y, a2h);
                }
            }
        }
    }
    if (ug < 15) {
        ulonglong2* po = (ulonglong2*)g_pout;
        size_t baseo = ((size_t)(bh * NC + c) * SSK) * 16 + d4;
        po[baseo + (size_t)u0 * 16]       = make_ulonglong2(a0l, a0h);
        po[baseo + (size_t)(u0 + 1) * 16] = make_ulonglong2(a1l, a1h);
        po[baseo + (size_t)(u0 + 2) * 16] = make_ulonglong2(a2l, a2h);
    }

    // ---- fused combine: last CTA of this bh merges partials and scatters ----
    __threadfence();
    __syncthreads();
    __shared__ int s_last;
    if (tid == 0) s_last = (atomicAdd(&g_cnt[bh], 1) == NC - 1) ? 1 : 0;
    __syncthreads();
    if (!s_last) return;
    __threadfence();

    for (int i = tid; i < SSK * 16; i += K3T) {
        int u = i >> 4, dq = i & 15;
        float gm = -1e30f;
        #pragma unroll
        for (int cc = 0; cc < NC; cc++)
            gm = fmaxf(gm, g_pmax[(bh * NC + cc) * SSK + u]);
        float denom = 0.f;
        float4 a = make_float4(0.f, 0.f, 0.f, 0.f);
        #pragma unroll
        for (int cc = 0; cc < NC; cc++) {
            float w = __expf(g_pmax[(bh * NC + cc) * SSK + u] - gm);
            denom += g_psum[(bh * NC + cc) * SSK + u] * w;
            float4 po = g_pout[((bh * NC + cc) * SSK + u) * 16 + dq];
            a.x += w * po.x; a.y += w * po.y; a.z += w * po.z; a.w += w * po.w;
        }
        float inv = 1.0f / denom;
        a.x *= inv; a.y *= inv; a.z *= inv; a.w *= inv;
        int lsel = tops[u];
        out4[((size_t)(b * Ll + lsel) * Hh + h) * 16 + dq] = a;
    }
}

// ---------------- launch ----------------
extern "C" void kernel_launch(void* const* d_in, const int* in_sizes, int n_in,
                              void* d_out, int out_size) {
    const float4* q4 = (const float4*)d_in[0];
    const float4* k4 = (const float4*)d_in[1];
    const float4* v4 = (const float4*)d_in[2];
    const void* idxp = d_in[n_in - 1];
    for (int i = 0; i < n_in; i++)
        if (in_sizes[i] == Ll * SSK) idxp = d_in[i];
    float4* out4 = (float4*)d_out;

    cudaFuncSetAttribute(k3_attn, cudaFuncAttributeMaxDynamicSharedMemorySize, K3_SMEM);

    int n4 = out_size / 4;
    k0_zero<<<(n4 + 255) / 256, 256>>>(out4, n4, (const unsigned*)idxp);
    k1_score<<<Bb * Ll / 4, 128>>>(q4, k4, idxp);
    k2_topk<<<BH, 256>>>();
    k3_attn<<<dim3(NC, BH), K3T, K3_SMEM>>>(q4, k4, v4, out4);
}